// round 6
// baseline (speedup 1.0000x reference)
#include <cuda_runtime.h>
#include <math.h>
#include <stdint.h>

#define Bb 16
#define Cc 32
#define Hh 128
#define Ww 128
#define HW 16384
#define Rr 8
#define OUTC 32

typedef unsigned long long ull;

// ---------------- scratch (device globals; no allocation) ----------------
__device__ __align__(16) float d_kern[Bb * Rr * 288 * 32];   // [b][r][c*9+kl][oo]
__device__ float          d_pool[Bb * Cc * 9];               // [b][c][kl]
__device__ float          d_gate[Bb * 576];                  // [b][rr*9+kl]
__device__ int            d_sync[Bb];                        // pool->gate tickets (reset each run)
__device__ __align__(16) float d_int[(size_t)Bb * HW * 32];  // channel-inner input [b][pix][c]
__device__ unsigned char  d_sel[Bb * HW];                    // r1 | r2<<3
__device__ int            d_segcnt[Bb * Rr * 64];
__device__ int            d_cnt[Bb * Rr];
__device__ unsigned short d_list[Bb * Rr * HW];              // pix | flags<<14 (sorted by pix)
__device__ __align__(16) float d_cat[(size_t)Bb * 64 * HW];  // CHANNEL-FIRST [b][ch][pix]
__device__ __align__(16) float d_wft[9 * 64 * 32];           // [kl][ch][o]

// ---------------- f32x2 helpers ----------------
__device__ __forceinline__ ull pack2(float v) {
    ull r; asm("mov.b64 %0, {%1, %1};" : "=l"(r) : "f"(v)); return r;
}
__device__ __forceinline__ ull ffma2(ull a, ull b, ull c) {
    ull d; asm("fma.rn.f32x2 %0, %1, %2, %3;" : "=l"(d) : "l"(a), "l"(b), "l"(c)); return d;
}

// ---------------- L1: pool (512 blocks) + gate (last block per b) ----------------
__global__ void __launch_bounds__(128) poolgate_kernel(
    const float* __restrict__ in,
    const float* __restrict__ w1, const float* __restrict__ b1) {
    int bc = blockIdx.x;
    int b = bc >> 5;
    int x = threadIdx.x;
    const float* img = in + (size_t)bc * HW;
    float rb0 = 0.f, rb1 = 0.f, rb2 = 0.f;
    #pragma unroll 4
    for (int yy = 0; yy < Hh; yy++) {
        float v = __ldg(img + yy * Ww + x);
        if (yy < 43) rb0 += v;
        if (yy >= 42 && yy < 86) rb1 += v;
        if (yy >= 85) rb2 += v;
    }
    __shared__ float srow[3][128];
    srow[0][x] = rb0; srow[1][x] = rb1; srow[2][x] = rb2;
    __syncthreads();
    if (x < 9) {
        int i = x / 3, j = x % 3;
        const int s[3] = {0, 42, 85}, e[3] = {43, 86, 128};
        const int span[3] = {43, 44, 43};
        float ssum = 0.f;
        for (int xx = s[j]; xx < e[j]; xx++) ssum += srow[i][xx];
        d_pool[bc * 9 + x] = ssum / (float)(span[i] * span[j]);
    }
    // ---- ticket: last block of this b computes the gate ----
    __syncthreads();
    __threadfence();
    __syncthreads();
    __shared__ int winner;
    if (x == 0) {
        int tk = atomicAdd(&d_sync[b], 1);
        winner = (tk == 31);
    }
    __syncthreads();
    if (winner) {
        __threadfence();
        for (int i = x; i < 576; i += 128) {
            int rr = i / 9, kl = i % 9;
            float s = __ldg(b1 + rr);
            #pragma unroll
            for (int c2 = 0; c2 < Cc; c2++)
                s += d_pool[(b * Cc + c2) * 9 + kl] * __ldg(w1 + rr * Cc + c2);
            d_gate[b * 576 + i] = 1.f / (1.f + expf(-s));
        }
        __syncthreads();
        if (x == 0) d_sync[b] = 0;   // reset for next graph replay
    }
}

// ---------------- L2: MEGA — kern gen | transpose | s1 select | wft ----------------
#define MEGA_KERN   4608
#define MEGA_TRANS  8192
#define MEGA_S1     1024
#define MEGA_WFT    72

__global__ void __launch_bounds__(256) mega_kernel(
    const float* __restrict__ in, const float* __restrict__ guide,
    const float* __restrict__ w2, const float* __restrict__ b2,
    const float* __restrict__ w_spa, const float* __restrict__ b_spa,
    const float* __restrict__ w_spec, const float* __restrict__ b_spec,
    const float* __restrict__ w_f) {
    int blk = blockIdx.x;
    int t = threadIdx.x;
    __shared__ float tt[32][33];
    __shared__ int scnt[Rr];

    if (blk < MEGA_KERN) {
        // ---- dynamic kernel generation ----
        int idx = blk * 256 + t;
        int oo = idx & 31;
        int ckl = (idx >> 5) % 288;
        int t2 = idx / (288 * 32);
        int r = t2 & 7;
        int b = t2 >> 3;
        int c = ckl / 9, kl = ckl % 9;
        int jj = r * 1024 + oo * 32 + c;
        float v = __ldg(b2 + jj);
        float4 wa = __ldg((const float4*)(w2 + jj * 8));
        float4 wb = __ldg((const float4*)(w2 + jj * 8 + 4));
        const float* gb = d_gate + b * 576 + r * 72 + kl;
        v += gb[0]  * wa.x + gb[9]  * wa.y + gb[18] * wa.z + gb[27] * wa.w;
        v += gb[36] * wb.x + gb[45] * wb.y + gb[54] * wb.z + gb[63] * wb.w;
        d_kern[idx] = v;
    } else if (blk < MEGA_KERN + MEGA_TRANS) {
        // ---- input transpose -> d_int[b][pix][c] ----
        int tb = blk - MEGA_KERN;
        int px0 = (tb & 511) * 32;
        int b = tb >> 9;
        int lane = t & 31, wr = t >> 5;
        #pragma unroll
        for (int i = 0; i < 4; i++) {
            int c = wr + i * 8;
            tt[c][lane] = __ldg(in + ((size_t)(b * Cc + c)) * HW + px0 + lane);
        }
        __syncthreads();
        #pragma unroll
        for (int i = 0; i < 4; i++) {
            int pr = wr + i * 8;
            d_int[((size_t)b * HW + px0 + pr) * 32 + lane] = tt[lane][pr];
        }
    } else if (blk < MEGA_KERN + MEGA_TRANS + MEGA_S1) {
        // ---- s1: argmax select + per-segment counts ----
        int sb = blk - (MEGA_KERN + MEGA_TRANS);
        int seg = sb & 63;
        int b = sb >> 6;
        int pix = seg * 256 + t;

        float gv[Cc];
        #pragma unroll
        for (int c = 0; c < Cc; c++)
            gv[c] = __ldg(guide + ((size_t)(b * Cc + c)) * HW + pix);

        float best1 = -1e30f, best2 = -1e30f;
        int r1 = 0, r2 = 0;
        for (int r = 0; r < Rr; r++) {
            float s1 = __ldg(b_spa + r), s2 = __ldg(b_spec + r);
            #pragma unroll
            for (int c = 0; c < Cc; c++) {
                s1 += gv[c] * __ldg(w_spa + r * Cc + c);
                s2 += gv[c] * __ldg(w_spec + r * Cc + c);
            }
            if (s1 > best1) { best1 = s1; r1 = r; }
            if (s2 > best2) { best2 = s2; r2 = r; }
        }
        d_sel[b * HW + pix] = (unsigned char)(r1 | (r2 << 3));

        if (t < Rr) scnt[t] = 0;
        __syncthreads();
        if (r1 == r2) atomicAdd(&scnt[r1], 1);
        else { atomicAdd(&scnt[r1], 1); atomicAdd(&scnt[r2], 1); }
        __syncthreads();
        if (t < Rr) d_segcnt[(b * Rr + t) * 64 + seg] = scnt[t];
    } else {
        // ---- fusion weight transpose: wft[kl][ch][o] ----
        int wb2 = blk - (MEGA_KERN + MEGA_TRANS + MEGA_S1);
        int idx = wb2 * 256 + t;
        int o = idx & 31, ch = (idx >> 5) & 63, kl = idx >> 11;
        d_wft[idx] = w_f[(o * 64 + ch) * 9 + kl];
    }
}

// ---------------- L3: s3 emit with inline segment scan (replaces s2+s3) ----------------
__global__ void __launch_bounds__(256) s3_emit_kernel() {
    int t = threadIdx.x, seg = blockIdx.x, b = blockIdx.y;
    int w = t >> 5, lane = t & 31;

    // warp w == region r: scan its 64 segment counts
    __shared__ int sbase[Rr];
    {
        int r = w;
        const int* row = d_segcnt + (b * Rr + r) * 64;
        int c0 = row[lane], c1 = row[32 + lane];
        int is0 = c0, is1 = c1;
        #pragma unroll
        for (int o = 1; o < 32; o <<= 1) {
            int v0 = __shfl_up_sync(0xFFFFFFFFu, is0, o);
            int v1 = __shfl_up_sync(0xFFFFFFFFu, is1, o);
            if (lane >= o) { is0 += v0; is1 += v1; }
        }
        int total0 = __shfl_sync(0xFFFFFFFFu, is0, 31);
        is1 += total0;
        int excl;
        if (seg == 0) excl = 0;
        else if (seg <= 32) excl = __shfl_sync(0xFFFFFFFFu, is0, seg - 1);
        else excl = __shfl_sync(0xFFFFFFFFu, is1, seg - 33);
        if (lane == 0) sbase[r] = excl;
        if (seg == 63 && lane == 31) d_cnt[b * Rr + r] = is1;
    }
    __syncthreads();

    int pix = seg * 256 + t;
    int sel = d_sel[b * HW + pix];
    int r1 = sel & 7, r2 = sel >> 3;

    __shared__ int wcnt[8][8];
    int rank1 = 0, rank2 = 0;
    unsigned ltm = (1u << lane) - 1u;
    #pragma unroll
    for (int r = 0; r < Rr; r++) {
        unsigned m = __ballot_sync(0xFFFFFFFFu, (r1 == r) || (r2 == r));
        if (lane == 0) wcnt[w][r] = __popc(m);
        if (r1 == r) rank1 = __popc(m & ltm);
        if (r2 == r) rank2 = __popc(m & ltm);
    }
    __syncthreads();
    int wb1 = 0, wb2 = 0;
    for (int w2 = 0; w2 < w; w2++) { wb1 += wcnt[w2][r1]; wb2 += wcnt[w2][r2]; }

    unsigned short pv = (unsigned short)pix;
    if (r1 == r2) {
        int off = sbase[r1] + wb1 + rank1;
        d_list[(b * Rr + r1) * HW + off] = (unsigned short)(pv | (3u << 14));
    } else {
        int off1 = sbase[r1] + wb1 + rank1;
        d_list[(b * Rr + r1) * HW + off1] = (unsigned short)(pv | (1u << 14));
        int off2 = sbase[r2] + wb2 + rank2;
        d_list[(b * Rr + r2) * HW + off2] = (unsigned short)(pv | (2u << 14));
    }
}

// ---------------- L4: dynconv (512 entries/block, slab loaded once) ----------------
__global__ void __launch_bounds__(256) dynconv_kernel() {
    int b = blockIdx.z, r = blockIdx.y;
    int cnt = d_cnt[b * Rr + r];
    if (blockIdx.x * 512 >= cnt) return;

    __shared__ __align__(16) float ks[288 * 32];   // [c*9+tap][oo]
    {
        const float4* kg = (const float4*)(d_kern + (size_t)(b * Rr + r) * 9216);
        float4* kd = (float4*)ks;
        #pragma unroll
        for (int i = 0; i < 9; i++) kd[threadIdx.x + 256 * i] = kg[threadIdx.x + 256 * i];
    }
    __syncthreads();

    int w = threadIdx.x >> 5, lane = threadIdx.x & 31;
    int p = lane & 15, gg = lane >> 4;     // gg selects oo half (16 oo)
    const unsigned short* lst = d_list + (b * Rr + r) * HW;
    const float* inb = d_int + (size_t)b * HW * 32;
    float* catb = d_cat + (size_t)b * 64 * HW;
    const float4 z4 = make_float4(0.f, 0.f, 0.f, 0.f);

    for (int half = 0; half < 2; half++) {
        int base = blockIdx.x * 512 + half * 256;
        if (base >= cnt) break;

        int e0 = base + w * 32 + p;
        int e1 = e0 + 16;
        int ent0 = (e0 < cnt) ? (int)lst[e0] : 0;
        int ent1 = (e1 < cnt) ? (int)lst[e1] : 0;
        int f0 = (e0 < cnt) ? (ent0 >> 14) : 0;
        int f1 = (e1 < cnt) ? (ent1 >> 14) : 0;
        int pix0 = ent0 & 0x3FFF, pix1 = ent1 & 0x3FFF;
        int y0 = pix0 >> 7, x0 = pix0 & 127;
        int y1 = pix1 >> 7, x1 = pix1 & 127;

        unsigned vm0 = 0, vm1 = 0;
        #pragma unroll
        for (int tap = 0; tap < 9; tap++) {
            int ky = tap / 3, kx = tap % 3;
            int ya = y0 + ky - 1, xa = x0 + kx - 1;
            int yb = y1 + ky - 1, xb = x1 + kx - 1;
            if ((unsigned)ya < 128u && (unsigned)xa < 128u) vm0 |= 1u << tap;
            if ((unsigned)yb < 128u && (unsigned)xb < 128u) vm1 |= 1u << tap;
        }
        const float* p0 = inb + ((long)(y0 - 1) * Ww + (x0 - 1)) * 32;
        const float* p1 = inb + ((long)(y1 - 1) * Ww + (x1 - 1)) * 32;

        ull acc0[8], acc1[8];
        #pragma unroll
        for (int u = 0; u < 8; u++) { acc0[u] = 0; acc1[u] = 0; }

        for (int cq = 0; cq < 8; cq++) {
            const float* kq = ks + cq * 4 * 288 + gg * 16;
            #pragma unroll
            for (int tap = 0; tap < 9; tap++) {
                const int ky = tap / 3, kx = tap % 3;
                const int off = (ky * Ww + kx) * 32 + cq * 4;
                float4 v0 = (vm0 >> tap & 1) ? __ldg((const float4*)(p0 + off)) : z4;
                float4 v1 = (vm1 >> tap & 1) ? __ldg((const float4*)(p1 + off)) : z4;
                #pragma unroll
                for (int ci = 0; ci < 4; ci++) {
                    const ulonglong2* wp = (const ulonglong2*)(kq + ci * 288 + tap * 32);
                    ulonglong2 wA = wp[0], wB = wp[1], wC = wp[2], wD = wp[3];
                    float vc0 = (ci == 0) ? v0.x : (ci == 1) ? v0.y : (ci == 2) ? v0.z : v0.w;
                    float vc1 = (ci == 0) ? v1.x : (ci == 1) ? v1.y : (ci == 2) ? v1.z : v1.w;
                    ull a0 = pack2(vc0), a1 = pack2(vc1);
                    acc0[0] = ffma2(a0, wA.x, acc0[0]); acc0[1] = ffma2(a0, wA.y, acc0[1]);
                    acc0[2] = ffma2(a0, wB.x, acc0[2]); acc0[3] = ffma2(a0, wB.y, acc0[3]);
                    acc0[4] = ffma2(a0, wC.x, acc0[4]); acc0[5] = ffma2(a0, wC.y, acc0[5]);
                    acc0[6] = ffma2(a0, wD.x, acc0[6]); acc0[7] = ffma2(a0, wD.y, acc0[7]);
                    acc1[0] = ffma2(a1, wA.x, acc1[0]); acc1[1] = ffma2(a1, wA.y, acc1[1]);
                    acc1[2] = ffma2(a1, wB.x, acc1[2]); acc1[3] = ffma2(a1, wB.y, acc1[3]);
                    acc1[4] = ffma2(a1, wC.x, acc1[4]); acc1[5] = ffma2(a1, wC.y, acc1[5]);
                    acc1[6] = ffma2(a1, wD.x, acc1[6]); acc1[7] = ffma2(a1, wD.y, acc1[7]);
                }
            }
        }

        const float* a0f = (const float*)acc0;
        const float* a1f = (const float*)acc1;
        int ob = gg * 16;
        if (f0 & 1) {
            #pragma unroll
            for (int u = 0; u < 16; u++) catb[(ob + u) * HW + pix0] = a0f[u];
        }
        if (f0 & 2) {
            #pragma unroll
            for (int u = 0; u < 16; u++) catb[(32 + ob + u) * HW + pix0] = a0f[u];
        }
        if (f1 & 1) {
            #pragma unroll
            for (int u = 0; u < 16; u++) catb[(ob + u) * HW + pix1] = a1f[u];
        }
        if (f1 & 2) {
            #pragma unroll
            for (int u = 0; u < 16; u++) catb[(32 + ob + u) * HW + pix1] = a1f[u];
        }
    }
}

// ---------------- L5: fusion conv 3x3 (64->32) + bias + residual ----------------
__global__ void __launch_bounds__(256) fusion_kernel(
    const float* __restrict__ in, const float* __restrict__ b_f,
    float* __restrict__ out) {
    extern __shared__ __align__(16) float ws[];   // [tap][ch][oo] = 18432 floats
    {
        const float4* wsrc = (const float4*)d_wft;
        float4* wdst = (float4*)ws;
        #pragma unroll
        for (int i = 0; i < 18; i++) wdst[threadIdx.x + 256 * i] = wsrc[threadIdx.x + 256 * i];
    }
    __syncthreads();

    int w = threadIdx.x >> 5, lane = threadIdx.x & 31;
    int b = blockIdx.z;
    int y = blockIdx.y * 4 + (w >> 1);
    int xh = (w & 1) * 64;
    int xa = xh + lane, xb2 = xh + 32 + lane;

    const float* catb = d_cat + (size_t)b * 64 * HW;

    ull acc0[16], acc1[16];
    #pragma unroll
    for (int u = 0; u < 16; u++) { acc0[u] = 0; acc1[u] = 0; }

    for (int ch = 0; ch < 64; ch++) {
        const float* chp = catb + (size_t)ch * HW;
        #pragma unroll
        for (int tap = 0; tap < 9; tap++) {
            const int ky = tap / 3, kx = tap % 3;
            int yy = y + ky - 1;
            bool rok = (unsigned)yy < (unsigned)Hh;
            const float* rowp = chp + yy * Ww;
            int xx0 = xa + kx - 1, xx1 = xb2 + kx - 1;
            float v0 = (rok && (unsigned)xx0 < (unsigned)Ww) ? __ldg(rowp + xx0) : 0.f;
            float v1 = (rok && (unsigned)xx1 < (unsigned)Ww) ? __ldg(rowp + xx1) : 0.f;
            ull a0 = pack2(v0), a1 = pack2(v1);
            const ulonglong2* wp = (const ulonglong2*)(ws + (tap * 64 + ch) * 32);
            #pragma unroll
            for (int q = 0; q < 8; q++) {
                ulonglong2 wq = wp[q];
                acc0[q * 2]     = ffma2(a0, wq.x, acc0[q * 2]);
                acc0[q * 2 + 1] = ffma2(a0, wq.y, acc0[q * 2 + 1]);
                acc1[q * 2]     = ffma2(a1, wq.x, acc1[q * 2]);
                acc1[q * 2 + 1] = ffma2(a1, wq.y, acc1[q * 2 + 1]);
            }
        }
    }

    const float* a0f = (const float*)acc0;
    const float* a1f = (const float*)acc1;
    long pix0 = (long)y * Ww + xa;
    long pix1 = (long)y * Ww + xb2;
    #pragma unroll
    for (int o = 0; o < 32; o++) {
        float bias = __ldg(b_f + o);
        size_t idx0 = ((size_t)(b * OUTC + o)) * HW + pix0;
        size_t idx1 = ((size_t)(b * OUTC + o)) * HW + pix1;
        out[idx0] = a0f[o] + bias + __ldg(in + idx0);
        out[idx1] = a1f[o] + bias + __ldg(in + idx1);
    }
}

// ---------------- launch ----------------
extern "C" void kernel_launch(void* const* d_in, const int* in_sizes, int n_in,
                              void* d_out, int out_size) {
    const float* input  = (const float*)d_in[0];
    const float* guide  = (const float*)d_in[1];
    const float* w1     = (const float*)d_in[2];
    const float* b1     = (const float*)d_in[3];
    const float* w2     = (const float*)d_in[4];
    const float* b2     = (const float*)d_in[5];
    const float* w_spa  = (const float*)d_in[6];
    const float* b_spa  = (const float*)d_in[7];
    const float* w_spec = (const float*)d_in[8];
    const float* b_spec = (const float*)d_in[9];
    const float* w_f    = (const float*)d_in[10];
    const float* b_f    = (const float*)d_in[11];
    float* out = (float*)d_out;

    cudaFuncSetAttribute(fusion_kernel, cudaFuncAttributeMaxDynamicSharedMemorySize, 73728);

    poolgate_kernel<<<Bb * Cc, 128>>>(input, w1, b1);
    mega_kernel<<<MEGA_KERN + MEGA_TRANS + MEGA_S1 + MEGA_WFT, 256>>>(
        input, guide, w2, b2, w_spa, b_spa, w_spec, b_spec, w_f);
    s3_emit_kernel<<<dim3(64, Bb), 256>>>();
    dynconv_kernel<<<dim3(64, Rr, Bb), 256>>>();
    fusion_kernel<<<dim3(1, 32, Bb), 256, 73728>>>(input, b_f, out);
}